// round 7
// baseline (speedup 1.0000x reference)
#include <cuda_runtime.h>
#include <cuda_fp16.h>
#include <math.h>

// ---------------- problem constants ----------------
#define NB    8      // batch
#define BCAP  32     // B_ input capsules
#define NC    32     // C_ output capsules
#define WIN   14
#define WOUT  6
#define WW    36     // WOUT*WOUT
#define BKK   288    // K*K*B_
#define CWW   1152   // C_*WOUT*WOUT
#define EPSV  1e-10f
#define HALF_LN2PI 0.91893853320467274178f
#define LOG2E 1.4426950408889634074f
#define FULLM 0xffffffffu

// ---------------- device scratch (static: allocation-free) ----------------
__device__ __half g_votes_h[(size_t)NB * CWW * BKK * 16];  // 81 MB fp16 votes [b][x][i][h]
__device__ float  g_ap[(size_t)NB * CWW * BKK];            // R numerators [b][x][i]
__device__ float  g_part[NB * 36 * BKK];                   // stage-1 partial sums
__device__ float  g_denom[NB * BKK];                       // denom[b][i]
__device__ unsigned int g_ticket[NB];                      // zero-init; reset by last block

__device__ __forceinline__ float4 rowmul(float4 wr, float4 p0, float4 p1, float4 p2, float4 p3) {
    float4 r;
    r.x = wr.x*p0.x + wr.y*p1.x + wr.z*p2.x + wr.w*p3.x;
    r.y = wr.x*p0.y + wr.y*p1.y + wr.z*p2.y + wr.w*p3.y;
    r.z = wr.x*p0.z + wr.y*p1.z + wr.z*p2.z + wr.w*p3.z;
    r.w = wr.x*p0.w + wr.y*p1.w + wr.z*p2.w + wr.w*p3.w;
    return r;
}

__device__ __forceinline__ unsigned int h2u(__half2 x) {
    return *reinterpret_cast<unsigned int*>(&x);
}

__device__ __forceinline__ float ex2f(float x) {
    float y;
    asm("ex2.approx.ftz.f32 %0, %1;" : "=f"(y) : "f"(x));
    return y;
}

// One block per output column. blockIdx.x = x = s*32 + c. 288 threads = 36 g x 8 q.
// Thread (g,q) owns V[i = g+36k, h=2q..2q+1] for k=0..7 (coalesced half2 loads).
// Fused statistics pass (sum Rw*V, Rw*V^2, Rw); sigma^2 = E[RwV^2]/S - mu^2.
// Warp-redundant tail: every warp computes mu/sig/a from the shared partials
// (bit-identical across warps) and distributes intra-warp via shuffles — no
// second barrier, no smem broadcast arrays.
// PHASE 0: compute+store fp16 votes first (R = 1/C). PHASE 1: mid iter. PHASE 2: outputs.
template <int PHASE>
__global__ __launch_bounds__(BKK, 5)
void em_kernel(const float* __restrict__ poses, const float* __restrict__ act,
               const float* __restrict__ Wt, const float* __restrict__ beta_v,
               const float* __restrict__ beta_a, const float* __restrict__ lam,
               float* __restrict__ out)
{
    const int x   = blockIdx.x;
    const int b   = blockIdx.y;
    const int c   = x & 31;
    const int s   = x >> 5;
    const int yw  = s / WOUT;
    const int xw  = s - yw * WOUT;
    const int t   = threadIdx.x;
    const int g   = t >> 3;        // 0..35
    const int q   = t & 7;         // 0..7 (h-pair)
    const int w   = t >> 5;        // warp 0..8
    const int lane = t & 31;
    const size_t colbase = (size_t)(b * CWW + x) * BKK;

    __shared__ float  Rw[BKK];
    __shared__ float2 redm[9][8];        // Rw*V partials (float[9][16] view)
    __shared__ float2 redv[9][8];        // Rw*V^2 partials
    __shared__ float  red2[9];           // Rw partials
    __shared__ float  red[BKK];          // p staging

    // ---- Rw fill (thread t <-> capsule i = t) ----
    const int i  = t;
    const int Bc = i / 9, uv = i - Bc * 9, u = uv / 3, v = uv - u * 3;
    const float av = act[((b * BCAP + Bc) * WIN + (2 * xw + u)) * WIN + (2 * yw + v)];

    if (PHASE == 0) {
        const float4* Pp = reinterpret_cast<const float4*>(
            poses + ((size_t)((b * BCAP + Bc) * WIN + (2 * xw + u)) * WIN + (2 * yw + v)) * 16);
        const float4* Wp = reinterpret_cast<const float4*>(
            Wt + (size_t)(((Bc * 3 + u) * 3 + v) * NC + c) * 16);
        float4 p0 = Pp[0], p1 = Pp[1], p2 = Pp[2], p3 = Pp[3];
        float4 w0 = Wp[0], w1 = Wp[1], w2 = Wp[2], w3 = Wp[3];
        float4 r0 = rowmul(w0, p0, p1, p2, p3);
        float4 r1 = rowmul(w1, p0, p1, p2, p3);
        float4 r2 = rowmul(w2, p0, p1, p2, p3);
        float4 r3 = rowmul(w3, p0, p1, p2, p3);
        uint4 u0 = make_uint4(h2u(__floats2half2_rn(r0.x, r0.y)), h2u(__floats2half2_rn(r0.z, r0.w)),
                              h2u(__floats2half2_rn(r1.x, r1.y)), h2u(__floats2half2_rn(r1.z, r1.w)));
        uint4 u1 = make_uint4(h2u(__floats2half2_rn(r2.x, r2.y)), h2u(__floats2half2_rn(r2.z, r2.w)),
                              h2u(__floats2half2_rn(r3.x, r3.y)), h2u(__floats2half2_rn(r3.z, r3.w)));
        uint4* vg = reinterpret_cast<uint4*>(g_votes_h + colbase * 16 + (size_t)i * 16);
        vg[0] = u0; vg[1] = u1;
        Rw[i] = (1.0f / 32.0f) * av;
    } else {
        const float R = g_ap[colbase + i] / (g_denom[b * BKK + i] + EPSV) + EPSV;
        Rw[i] = R * av;
    }
    __syncthreads();   // Rw visible; (PHASE 0) own votes visible block-wide

    // ---- load votes: 8x LDG.32 half2, perfectly coalesced ----
    float2 Vr[8];
    const __half2* vp = reinterpret_cast<const __half2*>(g_votes_h + colbase * 16) + q;
    #pragma unroll
    for (int k = 0; k < 8; k++) Vr[k] = __half22float2(vp[(g + 36 * k) * 8]);

    // ---- fused statistics pass: sum Rw*V, Rw*V^2, Rw ----
    float2 accm = make_float2(0.f, 0.f);
    float2 accv = make_float2(0.f, 0.f);
    float  accr = 0.f;
    #pragma unroll
    for (int k = 0; k < 8; k++) {
        const float rw = Rw[g + 36 * k];
        const float tx = rw * Vr[k].x;
        const float ty = rw * Vr[k].y;
        accm.x += tx;                 accm.y += ty;
        accv.x = fmaf(tx, Vr[k].x, accv.x);
        accv.y = fmaf(ty, Vr[k].y, accv.y);
        accr += rw;
    }
    accm.x += __shfl_xor_sync(FULLM, accm.x, 8);
    accm.y += __shfl_xor_sync(FULLM, accm.y, 8);
    accv.x += __shfl_xor_sync(FULLM, accv.x, 8);
    accv.y += __shfl_xor_sync(FULLM, accv.y, 8);
    accr   += __shfl_xor_sync(FULLM, accr,   8);
    accm.x += __shfl_xor_sync(FULLM, accm.x, 16);
    accm.y += __shfl_xor_sync(FULLM, accm.y, 16);
    accv.x += __shfl_xor_sync(FULLM, accv.x, 16);
    accv.y += __shfl_xor_sync(FULLM, accv.y, 16);
    accr   += __shfl_xor_sync(FULLM, accr,   16);
    if (lane < 8) {
        redm[w][lane] = accm;
        redv[w][lane] = accv;
        if (lane == 0) red2[w] = accr;
    }
    __syncthreads();

    // ---- warp-redundant tail: all warps compute identical stats from partials ----
    float muv = 0.f, il2v = 0.f, nlcv = 0.f, lsv = 0.f, srv = 0.f;
    {
        const float* rm = reinterpret_cast<const float*>(redm);
        const float* rv = reinterpret_cast<const float*>(redv);
        if (lane < 16) {
            float rsum = 0.f, vsum = 0.f, sr = 0.f;
            #pragma unroll
            for (int j = 0; j < 9; j++) {
                rsum += rm[j * 16 + lane];
                vsum += rv[j * 16 + lane];
                sr   += red2[j];
            }
            srv = sr;
            muv = rsum / sr;
            const float sig = fmaxf(vsum / sr - muv * muv, 1e-12f);
            lsv  = __logf(sqrtf(sig) + EPSV);
            il2v = (0.5f * LOG2E) / sig;
            nlcv = -(lsv + HALF_LN2PI) * LOG2E;
        }
    }
    float lsum = lsv;
    lsum += __shfl_xor_sync(FULLM, lsum, 1);
    lsum += __shfl_xor_sync(FULLM, lsum, 2);
    lsum += __shfl_xor_sync(FULLM, lsum, 4);
    lsum += __shfl_xor_sync(FULLM, lsum, 8);
    float aa = 0.f;
    if (lane == 0) {
        const float cost = srv * (16.f * beta_v[c] + lsum);
        const float z = lam[0] * (beta_a[c] - cost);
        aa = 1.f / (1.f + __expf(-z));
    }
    const float a_s = __shfl_sync(FULLM, aa, 0);

    if (PHASE == 2) {
        const int cww_out = c * WW + s;
        if (w == 0) {
            if (lane < 16) out[(size_t)(b * CWW + cww_out) * 16 + lane] = muv;
            if (lane == 0) out[(size_t)NB * CWW * 16 + b * CWW + cww_out] = a_s;
        }
        return;
    }

    // ---- distribute per-h constants intra-warp ----
    const float2 mu2 = make_float2(__shfl_sync(FULLM, muv,  2 * q),
                                   __shfl_sync(FULLM, muv,  2 * q + 1));
    const float2 il  = make_float2(__shfl_sync(FULLM, il2v, 2 * q),
                                   __shfl_sync(FULLM, il2v, 2 * q + 1));
    const float2 lc  = make_float2(__shfl_sync(FULLM, nlcv, 2 * q),
                                   __shfl_sync(FULLM, nlcv, 2 * q + 1));

    // ---- p-pass: ap[i] = a * sum_h exp2(-d^2*il2 + nlc2) ----
    #pragma unroll
    for (int k = 0; k < 8; k++) {
        const float dx = Vr[k].x - mu2.x;
        const float dy = Vr[k].y - mu2.y;
        float p = ex2f(fmaf(-dx * dx, il.x, lc.x)) + ex2f(fmaf(-dy * dy, il.y, lc.y));
        p += __shfl_xor_sync(FULLM, p, 1);
        p += __shfl_xor_sync(FULLM, p, 2);
        p += __shfl_xor_sync(FULLM, p, 4);
        if (q == 0) red[g + 36 * k] = p;
    }
    __syncthreads();
    g_ap[colbase + t] = a_s * red[t];   // one fully-coalesced 1152B store per block
}

// Fused denom: stage 1 partial sums + last-block-per-b final reduction.
// grid (36, NB), block 288. Deterministic (fixed j order in the final sum).
__global__ __launch_bounds__(BKK)
void denom_kernel()
{
    const int j = blockIdx.x;       // 0..35
    const int b = blockIdx.y;
    const int i = threadIdx.x;
    const float* ap = g_ap + (size_t)(b * CWW + j * 32) * BKK + i;
    float sv = 0.f;
    #pragma unroll 8
    for (int r = 0; r < 32; r++) sv += ap[(size_t)r * BKK];
    g_part[(b * 36 + j) * BKK + i] = sv;

    __threadfence();
    __shared__ unsigned int done;
    if (threadIdx.x == 0) done = atomicAdd(&g_ticket[b], 1u);
    __syncthreads();
    if (done == 35) {
        __threadfence();   // acquire all blocks' g_part writes
        const float* pp = g_part + b * 36 * BKK + i;
        float sm = 0.f;
        #pragma unroll
        for (int jj = 0; jj < 36; jj++) sm += pp[jj * BKK];
        g_denom[b * BKK + i] = sm;
        if (threadIdx.x == 0) g_ticket[b] = 0;   // reset for replay determinism
    }
}

extern "C" void kernel_launch(void* const* d_in, const int* in_sizes, int n_in,
                              void* d_out, int out_size)
{
    (void)in_sizes; (void)n_in; (void)out_size;
    const float* poses = (const float*)d_in[0];
    const float* act   = (const float*)d_in[1];
    const float* Wt    = (const float*)d_in[2];
    const float* bv    = (const float*)d_in[3];
    const float* ba    = (const float*)d_in[4];
    const float* lam   = (const float*)d_in[5];
    float* out = (float*)d_out;

    dim3 grid(CWW, NB);
    em_kernel<0><<<grid, BKK>>>(poses, act, Wt, bv, ba, lam, out);
    denom_kernel<<<dim3(36, NB), BKK>>>();
    em_kernel<1><<<grid, BKK>>>(poses, act, Wt, bv, ba, lam, out);
    denom_kernel<<<dim3(36, NB), BKK>>>();
    em_kernel<2><<<grid, BKK>>>(poses, act, Wt, bv, ba, lam, out);
}

// round 8
// speedup vs baseline: 1.0218x; 1.0218x over previous
#include <cuda_runtime.h>
#include <cuda_fp16.h>
#include <math.h>

// ---------------- problem constants ----------------
#define NB    8      // batch
#define BCAP  32     // B_ input capsules
#define NC    32     // C_ output capsules
#define WIN   14
#define WOUT  6
#define WW    36     // WOUT*WOUT
#define BKK   288    // K*K*B_
#define CWW   1152   // C_*WOUT*WOUT
#define EPSV  1e-10f
#define HALF_LN2PI 0.91893853320467274178f
#define LOG2E 1.4426950408889634074f

// ---------------- device scratch (static: allocation-free) ----------------
__device__ __half g_votes_h[(size_t)NB * CWW * BKK * 16];  // 81 MB fp16 votes [b][x][i][h]
__device__ float  g_ap[(size_t)NB * CWW * BKK];            // R numerators [b][x][i]
__device__ float  g_part[NB * 36 * BKK];                   // stage-1 partial sums
__device__ float  g_denom[NB * BKK];                       // denom[b][i]

__device__ __forceinline__ float4 rowmul(float4 wr, float4 p0, float4 p1, float4 p2, float4 p3) {
    float4 r;
    r.x = wr.x*p0.x + wr.y*p1.x + wr.z*p2.x + wr.w*p3.x;
    r.y = wr.x*p0.y + wr.y*p1.y + wr.z*p2.y + wr.w*p3.y;
    r.z = wr.x*p0.z + wr.y*p1.z + wr.z*p2.z + wr.w*p3.z;
    r.w = wr.x*p0.w + wr.y*p1.w + wr.z*p2.w + wr.w*p3.w;
    return r;
}

__device__ __forceinline__ unsigned int h2u(__half2 x) {
    return *reinterpret_cast<unsigned int*>(&x);
}

__device__ __forceinline__ float ex2f(float x) {
    float y;
    asm("ex2.approx.ftz.f32 %0, %1;" : "=f"(y) : "f"(x));
    return y;
}

// One block per output column. blockIdx.x = x = s*32 + c. 288 threads = 36 g x 8 q.
// Thread (g,q) owns V[i = g+36k, h=2q..2q+1] for k=0..7 (coalesced half2 loads).
// Single fused statistics pass: accumulate Rw*V, Rw*V^2, Rw; sigma^2 = E[RwV^2]/S - mu^2.
// PHASE 0: compute+store fp16 votes first (R = 1/C). PHASE 1: mid iter. PHASE 2: outputs.
template <int PHASE>
__global__ __launch_bounds__(BKK, 6)
void em_kernel(const float* __restrict__ poses, const float* __restrict__ act,
               const float* __restrict__ Wt, const float* __restrict__ beta_v,
               const float* __restrict__ beta_a, const float* __restrict__ lam,
               float* __restrict__ out)
{
    const int x   = blockIdx.x;
    const int b   = blockIdx.y;
    const int c   = x & 31;
    const int s   = x >> 5;
    const int yw  = s / WOUT;
    const int xw  = s - yw * WOUT;
    const int t   = threadIdx.x;
    const int g   = t >> 3;        // 0..35
    const int q   = t & 7;         // 0..7 (h-pair)
    const int w   = t >> 5;        // warp 0..8
    const int lane = t & 31;
    const size_t colbase = (size_t)(b * CWW + x) * BKK;

    __shared__ float  Rw[BKK];
    __shared__ float2 redm[9][8];        // Rw*V partials (float[9][16] view)
    __shared__ float2 redv[9][8];        // Rw*V^2 partials
    __shared__ float  red2[9];           // Rw partials
    __shared__ float  red[BKK];          // p staging
    __shared__ float  mu_s[16], il2_s[16], nlc2_s[16];
    __shared__ float  sumR_s, a_s;

    // ---- Rw fill (thread t <-> capsule i = t) ----
    const int i  = t;
    const int Bc = i / 9, uv = i - Bc * 9, u = uv / 3, v = uv - u * 3;
    const float av = act[((b * BCAP + Bc) * WIN + (2 * xw + u)) * WIN + (2 * yw + v)];

    if (PHASE == 0) {
        const float4* Pp = reinterpret_cast<const float4*>(
            poses + ((size_t)((b * BCAP + Bc) * WIN + (2 * xw + u)) * WIN + (2 * yw + v)) * 16);
        const float4* Wp = reinterpret_cast<const float4*>(
            Wt + (size_t)(((Bc * 3 + u) * 3 + v) * NC + c) * 16);
        float4 p0 = Pp[0], p1 = Pp[1], p2 = Pp[2], p3 = Pp[3];
        float4 w0 = Wp[0], w1 = Wp[1], w2 = Wp[2], w3 = Wp[3];
        float4 r0 = rowmul(w0, p0, p1, p2, p3);
        float4 r1 = rowmul(w1, p0, p1, p2, p3);
        float4 r2 = rowmul(w2, p0, p1, p2, p3);
        float4 r3 = rowmul(w3, p0, p1, p2, p3);
        uint4 u0 = make_uint4(h2u(__floats2half2_rn(r0.x, r0.y)), h2u(__floats2half2_rn(r0.z, r0.w)),
                              h2u(__floats2half2_rn(r1.x, r1.y)), h2u(__floats2half2_rn(r1.z, r1.w)));
        uint4 u1 = make_uint4(h2u(__floats2half2_rn(r2.x, r2.y)), h2u(__floats2half2_rn(r2.z, r2.w)),
                              h2u(__floats2half2_rn(r3.x, r3.y)), h2u(__floats2half2_rn(r3.z, r3.w)));
        uint4* vg = reinterpret_cast<uint4*>(g_votes_h + colbase * 16 + (size_t)i * 16);
        vg[0] = u0; vg[1] = u1;
        Rw[i] = (1.0f / 32.0f) * av;
    } else {
        const float R = g_ap[colbase + i] / (g_denom[b * BKK + i] + EPSV) + EPSV;
        Rw[i] = R * av;
    }
    __syncthreads();   // Rw visible; (PHASE 0) own votes visible block-wide

    // ---- load votes: 8x LDG.32 half2, perfectly coalesced ----
    float2 Vr[8];
    const __half2* vp = reinterpret_cast<const __half2*>(g_votes_h + colbase * 16) + q;
    #pragma unroll
    for (int k = 0; k < 8; k++) Vr[k] = __half22float2(vp[(g + 36 * k) * 8]);

    // ---- fused statistics pass: sum Rw*V, Rw*V^2, Rw ----
    float2 accm = make_float2(0.f, 0.f);
    float2 accv = make_float2(0.f, 0.f);
    float  accr = 0.f;
    #pragma unroll
    for (int k = 0; k < 8; k++) {
        const float rw = Rw[g + 36 * k];
        const float tx = rw * Vr[k].x;
        const float ty = rw * Vr[k].y;
        accm.x += tx;                 accm.y += ty;
        accv.x = fmaf(tx, Vr[k].x, accv.x);
        accv.y = fmaf(ty, Vr[k].y, accv.y);
        accr += rw;
    }
    accm.x += __shfl_xor_sync(0xffffffffu, accm.x, 8);
    accm.y += __shfl_xor_sync(0xffffffffu, accm.y, 8);
    accv.x += __shfl_xor_sync(0xffffffffu, accv.x, 8);
    accv.y += __shfl_xor_sync(0xffffffffu, accv.y, 8);
    accr   += __shfl_xor_sync(0xffffffffu, accr,   8);
    accm.x += __shfl_xor_sync(0xffffffffu, accm.x, 16);
    accm.y += __shfl_xor_sync(0xffffffffu, accm.y, 16);
    accv.x += __shfl_xor_sync(0xffffffffu, accv.x, 16);
    accv.y += __shfl_xor_sync(0xffffffffu, accv.y, 16);
    accr   += __shfl_xor_sync(0xffffffffu, accr,   16);
    if (lane < 8) {
        redm[w][lane] = accm;
        redv[w][lane] = accv;
        if (lane == 0) red2[w] = accr;
    }
    __syncthreads();

    if (t < 16) {
        const float* rm = reinterpret_cast<const float*>(redm);
        const float* rv = reinterpret_cast<const float*>(redv);
        float rsum = 0.f, vsum = 0.f, sr = 0.f;
        #pragma unroll
        for (int j = 0; j < 9; j++) {
            rsum += rm[j * 16 + t];
            vsum += rv[j * 16 + t];
            sr   += red2[j];
        }
        if (t == 0) sumR_s = sr;
        const float mu  = rsum / sr;
        mu_s[t] = mu;
        float sig = fmaxf(vsum / sr - mu * mu, 1e-12f);
        const float ls = __logf(sqrtf(sig) + EPSV);
        il2_s[t]  = (0.5f * LOG2E) / sig;
        nlc2_s[t] = -(ls + HALF_LN2PI) * LOG2E;
        // activation via in-warp reduce over the 16 active lanes (all in warp 0)
        float lsum = ls;
        lsum += __shfl_xor_sync(0x0000ffffu, lsum, 1);
        lsum += __shfl_xor_sync(0x0000ffffu, lsum, 2);
        lsum += __shfl_xor_sync(0x0000ffffu, lsum, 4);
        lsum += __shfl_xor_sync(0x0000ffffu, lsum, 8);
        if (t == 0) {
            const float cost = sr * (16.f * beta_v[c] + lsum);
            const float z = lam[0] * (beta_a[c] - cost);
            a_s = 1.f / (1.f + __expf(-z));
        }
    }
    __syncthreads();

    if (PHASE == 2) {
        const int cww_out = c * WW + s;
        if (t < 16) out[(size_t)(b * CWW + cww_out) * 16 + t] = mu_s[t];
        if (t == 0) out[(size_t)NB * CWW * 16 + b * CWW + cww_out] = a_s;
        return;
    }

    // ---- p-pass: ap[i] = a * sum_h exp2(-d^2*il2 + nlc2) ----
    const float2 mu2 = make_float2(mu_s[2 * q], mu_s[2 * q + 1]);
    const float2 il  = make_float2(il2_s[2 * q], il2_s[2 * q + 1]);
    const float2 lc  = make_float2(nlc2_s[2 * q], nlc2_s[2 * q + 1]);
    #pragma unroll
    for (int k = 0; k < 8; k++) {
        const float dx = Vr[k].x - mu2.x;
        const float dy = Vr[k].y - mu2.y;
        float p = ex2f(fmaf(-dx * dx, il.x, lc.x)) + ex2f(fmaf(-dy * dy, il.y, lc.y));
        p += __shfl_xor_sync(0xffffffffu, p, 1);
        p += __shfl_xor_sync(0xffffffffu, p, 2);
        p += __shfl_xor_sync(0xffffffffu, p, 4);
        if (q == 0) red[g + 36 * k] = p;
    }
    __syncthreads();
    g_ap[colbase + t] = a_s * red[t];   // one fully-coalesced 1152B store per block
}

// Stage 1: block (j,b) sums 32 consecutive x-rows of ap -> g_part[b][j][i].
// 288 blocks, coalesced loads, 32 independent loads/thread (high MLP).
__global__ __launch_bounds__(BKK)
void denom_part_kernel()
{
    const int j = blockIdx.x;       // 0..35
    const int b = blockIdx.y;
    const int i = threadIdx.x;
    const float* ap = g_ap + (size_t)(b * CWW + j * 32) * BKK + i;
    float sv = 0.f;
    #pragma unroll 8
    for (int r = 0; r < 32; r++) sv += ap[(size_t)r * BKK];
    g_part[(b * 36 + j) * BKK + i] = sv;
}

// Stage 2: denom[b][i] = sum of the 36 partials. Tiny (331 KB read).
__global__ __launch_bounds__(BKK)
void denom_final_kernel()
{
    const int b = blockIdx.x;
    const int i = threadIdx.x;
    const float* pp = g_part + b * 36 * BKK + i;
    float sv = 0.f;
    #pragma unroll
    for (int j = 0; j < 36; j++) sv += pp[j * BKK];
    g_denom[b * BKK + i] = sv;
}

extern "C" void kernel_launch(void* const* d_in, const int* in_sizes, int n_in,
                              void* d_out, int out_size)
{
    (void)in_sizes; (void)n_in; (void)out_size;
    const float* poses = (const float*)d_in[0];
    const float* act   = (const float*)d_in[1];
    const float* Wt    = (const float*)d_in[2];
    const float* bv    = (const float*)d_in[3];
    const float* ba    = (const float*)d_in[4];
    const float* lam   = (const float*)d_in[5];
    float* out = (float*)d_out;

    dim3 grid(CWW, NB);
    em_kernel<0><<<grid, BKK>>>(poses, act, Wt, bv, ba, lam, out);
    denom_part_kernel<<<dim3(36, NB), BKK>>>();
    denom_final_kernel<<<NB, BKK>>>();
    em_kernel<1><<<grid, BKK>>>(poses, act, Wt, bv, ba, lam, out);
    denom_part_kernel<<<dim3(36, NB), BKK>>>();
    denom_final_kernel<<<NB, BKK>>>();
    em_kernel<2><<<grid, BKK>>>(poses, act, Wt, bv, ba, lam, out);
}

// round 9
// speedup vs baseline: 1.0946x; 1.0712x over previous
#include <cuda_runtime.h>
#include <cuda_fp16.h>
#include <math.h>

// ---------------- problem constants ----------------
#define NB    8      // batch
#define BCAP  32     // B_ input capsules
#define NC    32     // C_ output capsules
#define WIN   14
#define WOUT  6
#define WW    36     // WOUT*WOUT
#define BKK   288    // K*K*B_
#define CWW   1152   // C_*WOUT*WOUT
#define EPSV  1e-10f
#define HALF_LN2PI 0.91893853320467274178f
#define LOG2E 1.4426950408889634074f

// ---------------- device scratch (static: allocation-free) ----------------
__device__ __half g_votes_h[(size_t)NB * CWW * BKK * 16];  // 81 MB fp16 votes [b][x][i][h]
__device__ float  g_ap[(size_t)NB * CWW * BKK];            // R numerators [b][x][i]
__device__ float  g_part[NB * 36 * BKK];                   // stage-1 partial sums
__device__ float  g_denom[NB * BKK];                       // denom[b][i]

__device__ __forceinline__ float4 rowmul(float4 wr, float4 p0, float4 p1, float4 p2, float4 p3) {
    float4 r;
    r.x = wr.x*p0.x + wr.y*p1.x + wr.z*p2.x + wr.w*p3.x;
    r.y = wr.x*p0.y + wr.y*p1.y + wr.z*p2.y + wr.w*p3.y;
    r.z = wr.x*p0.z + wr.y*p1.z + wr.z*p2.z + wr.w*p3.z;
    r.w = wr.x*p0.w + wr.y*p1.w + wr.z*p2.w + wr.w*p3.w;
    return r;
}

__device__ __forceinline__ unsigned int h2u(__half2 x) {
    return *reinterpret_cast<unsigned int*>(&x);
}

__device__ __forceinline__ float ex2f(float x) {
    float y;
    asm("ex2.approx.ftz.f32 %0, %1;" : "=f"(y) : "f"(x));
    return y;
}

// One block per output column. blockIdx.x = x = s*32 + c. 288 threads = 36 g x 8 q.
// Thread (g,q) owns V[i = g+36k, h=2q..2q+1] for k=0..7 (coalesced half2 loads).
// Votes are PREFETCHED as raw half2 before the Rw fill so their DRAM latency
// overlaps the Rw computation and the barrier. Fused statistics pass
// (sum Rw*V, Rw*V^2, Rw); sigma^2 = E[RwV^2]/S - mu^2.
// p-pass stores g_ap directly (q==0 lanes per warp form one 16B segment).
// PHASE 0: compute+store fp16 votes first (R = 1/C). PHASE 1: mid iter. PHASE 2: outputs.
template <int PHASE>
__global__ __launch_bounds__(BKK, 5)
void em_kernel(const float* __restrict__ poses, const float* __restrict__ act,
               const float* __restrict__ Wt, const float* __restrict__ beta_v,
               const float* __restrict__ beta_a, const float* __restrict__ lam,
               float* __restrict__ out)
{
    const int x   = blockIdx.x;
    const int b   = blockIdx.y;
    const int c   = x & 31;
    const int s   = x >> 5;
    const int yw  = s / WOUT;
    const int xw  = s - yw * WOUT;
    const int t   = threadIdx.x;
    const int g   = t >> 3;        // 0..35
    const int q   = t & 7;         // 0..7 (h-pair)
    const int w   = t >> 5;        // warp 0..8
    const int lane = t & 31;
    const size_t colbase = (size_t)(b * CWW + x) * BKK;

    __shared__ float  Rw[BKK];
    __shared__ float2 redm[9][8];        // Rw*V partials (float[9][16] view)
    __shared__ float2 redv[9][8];        // Rw*V^2 partials
    __shared__ float  red2[9];           // Rw partials
    __shared__ float  mu_s[16], il2_s[16], nlc2_s[16];
    __shared__ float  sumR_s, a_s;

    // ---- Rw fill (thread t <-> capsule i = t) ----
    const int i  = t;
    const int Bc = i / 9, uv = i - Bc * 9, u = uv / 3, v = uv - u * 3;
    const float av = act[((b * BCAP + Bc) * WIN + (2 * xw + u)) * WIN + (2 * yw + v)];

    float2 Vr[8];
    const __half2* vp = reinterpret_cast<const __half2*>(g_votes_h + colbase * 16) + q;

    if (PHASE == 0) {
        const float4* Pp = reinterpret_cast<const float4*>(
            poses + ((size_t)((b * BCAP + Bc) * WIN + (2 * xw + u)) * WIN + (2 * yw + v)) * 16);
        const float4* Wp = reinterpret_cast<const float4*>(
            Wt + (size_t)(((Bc * 3 + u) * 3 + v) * NC + c) * 16);
        float4 p0 = Pp[0], p1 = Pp[1], p2 = Pp[2], p3 = Pp[3];
        float4 w0 = Wp[0], w1 = Wp[1], w2 = Wp[2], w3 = Wp[3];
        float4 r0 = rowmul(w0, p0, p1, p2, p3);
        float4 r1 = rowmul(w1, p0, p1, p2, p3);
        float4 r2 = rowmul(w2, p0, p1, p2, p3);
        float4 r3 = rowmul(w3, p0, p1, p2, p3);
        uint4 u0 = make_uint4(h2u(__floats2half2_rn(r0.x, r0.y)), h2u(__floats2half2_rn(r0.z, r0.w)),
                              h2u(__floats2half2_rn(r1.x, r1.y)), h2u(__floats2half2_rn(r1.z, r1.w)));
        uint4 u1 = make_uint4(h2u(__floats2half2_rn(r2.x, r2.y)), h2u(__floats2half2_rn(r2.z, r2.w)),
                              h2u(__floats2half2_rn(r3.x, r3.y)), h2u(__floats2half2_rn(r3.z, r3.w)));
        uint4* vg = reinterpret_cast<uint4*>(g_votes_h + colbase * 16 + (size_t)i * 16);
        vg[0] = u0; vg[1] = u1;
        Rw[i] = (1.0f / 32.0f) * av;
        __syncthreads();   // votes visible block-wide; Rw visible
        #pragma unroll
        for (int k = 0; k < 8; k++) Vr[k] = __half22float2(vp[(g + 36 * k) * 8]);
    } else {
        // prefetch votes FIRST (independent) so latency overlaps Rw fill + barrier
        __half2 vh[8];
        #pragma unroll
        for (int k = 0; k < 8; k++) vh[k] = vp[(g + 36 * k) * 8];
        const float R = g_ap[colbase + i] / (g_denom[b * BKK + i] + EPSV) + EPSV;
        Rw[i] = R * av;
        __syncthreads();
        #pragma unroll
        for (int k = 0; k < 8; k++) Vr[k] = __half22float2(vh[k]);
    }

    // ---- fused statistics pass: sum Rw*V, Rw*V^2, Rw ----
    float2 accm = make_float2(0.f, 0.f);
    float2 accv = make_float2(0.f, 0.f);
    float  accr = 0.f;
    #pragma unroll
    for (int k = 0; k < 8; k++) {
        const float rw = Rw[g + 36 * k];
        const float tx = rw * Vr[k].x;
        const float ty = rw * Vr[k].y;
        accm.x += tx;                 accm.y += ty;
        accv.x = fmaf(tx, Vr[k].x, accv.x);
        accv.y = fmaf(ty, Vr[k].y, accv.y);
        accr += rw;
    }
    accm.x += __shfl_xor_sync(0xffffffffu, accm.x, 8);
    accm.y += __shfl_xor_sync(0xffffffffu, accm.y, 8);
    accv.x += __shfl_xor_sync(0xffffffffu, accv.x, 8);
    accv.y += __shfl_xor_sync(0xffffffffu, accv.y, 8);
    accr   += __shfl_xor_sync(0xffffffffu, accr,   8);
    accm.x += __shfl_xor_sync(0xffffffffu, accm.x, 16);
    accm.y += __shfl_xor_sync(0xffffffffu, accm.y, 16);
    accv.x += __shfl_xor_sync(0xffffffffu, accv.x, 16);
    accv.y += __shfl_xor_sync(0xffffffffu, accv.y, 16);
    accr   += __shfl_xor_sync(0xffffffffu, accr,   16);
    if (lane < 8) {
        redm[w][lane] = accm;
        redv[w][lane] = accv;
        if (lane == 0) red2[w] = accr;
    }
    __syncthreads();

    if (t < 16) {
        const float* rm = reinterpret_cast<const float*>(redm);
        const float* rv = reinterpret_cast<const float*>(redv);
        float rsum = 0.f, vsum = 0.f, sr = 0.f;
        #pragma unroll
        for (int j = 0; j < 9; j++) {
            rsum += rm[j * 16 + t];
            vsum += rv[j * 16 + t];
            sr   += red2[j];
        }
        if (t == 0) sumR_s = sr;
        const float mu  = rsum / sr;
        mu_s[t] = mu;
        float sig = fmaxf(vsum / sr - mu * mu, 1e-12f);
        const float ls = __logf(sqrtf(sig) + EPSV);
        il2_s[t]  = (0.5f * LOG2E) / sig;
        nlc2_s[t] = -(ls + HALF_LN2PI) * LOG2E;
        // activation via in-warp reduce over the 16 active lanes (all in warp 0)
        float lsum = ls;
        lsum += __shfl_xor_sync(0x0000ffffu, lsum, 1);
        lsum += __shfl_xor_sync(0x0000ffffu, lsum, 2);
        lsum += __shfl_xor_sync(0x0000ffffu, lsum, 4);
        lsum += __shfl_xor_sync(0x0000ffffu, lsum, 8);
        if (t == 0) {
            const float cost = sr * (16.f * beta_v[c] + lsum);
            const float z = lam[0] * (beta_a[c] - cost);
            a_s = 1.f / (1.f + __expf(-z));
        }
    }
    __syncthreads();

    if (PHASE == 2) {
        const int cww_out = c * WW + s;
        if (t < 16) out[(size_t)(b * CWW + cww_out) * 16 + t] = mu_s[t];
        if (t == 0) out[(size_t)NB * CWW * 16 + b * CWW + cww_out] = a_s;
        return;
    }

    // ---- p-pass: ap[i] = a * sum_h exp2(-d^2*il2 + nlc2); direct 16B-segment stores ----
    const float  an  = a_s;
    const float2 mu2 = make_float2(mu_s[2 * q], mu_s[2 * q + 1]);
    const float2 il  = make_float2(il2_s[2 * q], il2_s[2 * q + 1]);
    const float2 lc  = make_float2(nlc2_s[2 * q], nlc2_s[2 * q + 1]);
    #pragma unroll
    for (int k = 0; k < 8; k++) {
        const float dx = Vr[k].x - mu2.x;
        const float dy = Vr[k].y - mu2.y;
        float p = ex2f(fmaf(-dx * dx, il.x, lc.x)) + ex2f(fmaf(-dy * dy, il.y, lc.y));
        p += __shfl_xor_sync(0xffffffffu, p, 1);
        p += __shfl_xor_sync(0xffffffffu, p, 2);
        p += __shfl_xor_sync(0xffffffffu, p, 4);
        // q==0 lanes of a warp are g = 4w..4w+3 -> 4 consecutive floats = one 16B segment
        if (q == 0) g_ap[colbase + g + 36 * k] = an * p;
    }
}

// Stage 1: block (j,b) sums 32 consecutive x-rows of ap -> g_part[b][j][i].
// 288 blocks, coalesced loads, 32 independent loads/thread (high MLP).
__global__ __launch_bounds__(BKK)
void denom_part_kernel()
{
    const int j = blockIdx.x;       // 0..35
    const int b = blockIdx.y;
    const int i = threadIdx.x;
    const float* ap = g_ap + (size_t)(b * CWW + j * 32) * BKK + i;
    float sv = 0.f;
    #pragma unroll 8
    for (int r = 0; r < 32; r++) sv += ap[(size_t)r * BKK];
    g_part[(b * 36 + j) * BKK + i] = sv;
}

// Stage 2: denom[b][i] = sum of the 36 partials. Tiny (331 KB read).
__global__ __launch_bounds__(BKK)
void denom_final_kernel()
{
    const int b = blockIdx.x;
    const int i = threadIdx.x;
    const float* pp = g_part + b * 36 * BKK + i;
    float sv = 0.f;
    #pragma unroll
    for (int j = 0; j < 36; j++) sv += pp[j * BKK];
    g_denom[b * BKK + i] = sv;
}

extern "C" void kernel_launch(void* const* d_in, const int* in_sizes, int n_in,
                              void* d_out, int out_size)
{
    (void)in_sizes; (void)n_in; (void)out_size;
    const float* poses = (const float*)d_in[0];
    const float* act   = (const float*)d_in[1];
    const float* Wt    = (const float*)d_in[2];
    const float* bv    = (const float*)d_in[3];
    const float* ba    = (const float*)d_in[4];
    const float* lam   = (const float*)d_in[5];
    float* out = (float*)d_out;

    dim3 grid(CWW, NB);
    em_kernel<0><<<grid, BKK>>>(poses, act, Wt, bv, ba, lam, out);
    denom_part_kernel<<<dim3(36, NB), BKK>>>();
    denom_final_kernel<<<NB, BKK>>>();
    em_kernel<1><<<grid, BKK>>>(poses, act, Wt, bv, ba, lam, out);
    denom_part_kernel<<<dim3(36, NB), BKK>>>();
    denom_final_kernel<<<NB, BKK>>>();
    em_kernel<2><<<grid, BKK>>>(poses, act, Wt, bv, ba, lam, out);
}